// round 12
// baseline (speedup 1.0000x reference)
#include <cuda_runtime.h>
#include <cuda_fp16.h>
#include <stdint.h>
#include <math.h>

#define FDIM 512
#define NADJ 512
#define MROWS 65536

// ======================= helpers =======================
__device__ __forceinline__ uint32_t smem_u32(const void* p) {
    uint32_t a;
    asm("{ .reg .u64 t; cvta.to.shared.u64 t, %1; cvt.u32.u64 %0, t; }" : "=r"(a) : "l"(p));
    return a;
}
#define CP_ASYNC16(sa, ga) asm volatile("cp.async.cg.shared.global [%0], [%1], 16;" :: "r"(sa), "l"(ga) : "memory")
#define CP_COMMIT()        asm volatile("cp.async.commit_group;" ::: "memory")
#define CP_WAIT(n)         asm volatile("cp.async.wait_group %0;" :: "n"(n) : "memory")

#define LDSM4(r0, r1, r2, r3, addr) \
    asm volatile("ldmatrix.sync.aligned.m8n8.x4.shared.b16 {%0,%1,%2,%3}, [%4];" \
        : "=r"(r0), "=r"(r1), "=r"(r2), "=r"(r3) : "r"(addr))

#define MMA16816(d, a, b0, b1) \
    asm volatile("mma.sync.aligned.m16n8k16.row.col.f32.f16.f16.f32 " \
        "{%0,%1,%2,%3}, {%4,%5,%6,%7}, {%8,%9}, {%0,%1,%2,%3};" \
        : "+f"((d)[0]), "+f"((d)[1]), "+f"((d)[2]), "+f"((d)[3]) \
        : "r"((a)[0]), "r"((a)[1]), "r"((a)[2]), "r"((a)[3]), "r"(b0), "r"(b1))

__device__ __forceinline__ uint32_t pack2h(float a, float b) {
    __half2 t = __floats2half2_rn(a, b);
    return *reinterpret_cast<uint32_t*>(&t);
}

// ======================= device scratch =======================
__device__ __half g_h1s[(size_t)MROWS * 512];   // h1 as fp16
__device__ __half g_b1s[NADJ * 512];            // W1 fp16
__device__ __half g_b2s[NADJ * 512];            // W2 fp16
__device__ float g_cpart[4][(size_t)MROWS * 2];
__device__ float g_dinv[NADJ];
__device__ float g_sb[4 * FDIM];   // s1, t1, s2, t2

// ======================= fused prep kernel (no d-conversion) =======================
// blocks [0, 2048)     : convert W1/W2 -> fp16
// block  2048          : fold BN affine scales
// blocks [2049, 2561)  : adjacency row sums -> dinv
#define PREP_BLOCKS (2048 + 1 + NADJ)
__global__ void prep_mega(const float* __restrict__ w,
                          const float* __restrict__ W1f, const float* __restrict__ W2f,
                          const float* b1, const float* g1, const float* be1,
                          const float* m1, const float* v1,
                          const float* b2, const float* g2, const float* be2,
                          const float* m2, const float* v2) {
    const int blk = blockIdx.x;
    const int tid = threadIdx.x;
    if (blk < 2048) {
        int which = blk >= 1024;
        int idx = (blk & 1023) * 256 + tid;
        const float* W = which ? W2f : W1f;
        __half* out = which ? g_b2s : g_b1s;
        out[idx] = __float2half(W[idx]);
    } else if (blk == 2048) {
        for (int f = tid; f < FDIM; f += 256) {
            float s1 = g1[f] * rsqrtf(v1[f] + 1e-5f);
            g_sb[f]        = s1;
            g_sb[FDIM + f] = (b1[f] - m1[f]) * s1 + be1[f];
            float s2 = g2[f] * rsqrtf(v2[f] + 1e-5f);
            g_sb[2*FDIM + f] = s2;
            g_sb[3*FDIM + f] = (b2[f] - m2[f]) * s2 + be2[f];
        }
    } else {
        __shared__ float red[256];
        int i = blk - 2049;
        float s = w[i * NADJ + tid] + w[i * NADJ + 256 + tid];
        red[tid] = s;
        __syncthreads();
        for (int o = 128; o > 0; o >>= 1) {
            if (tid < o) red[tid] += red[tid + o];
            __syncthreads();
        }
        if (tid == 0) {
            float di = rsqrtf(red[0] + 1.0f);
            if (isinf(di)) di = 0.f;
            g_dinv[i] = di;
        }
    }
}

// ======================= HMMA GEMM (pure fp16) =======================
// C[128 x 128] per block. K = 512 in 16 k-tiles of 32.
// 128 threads = 4 warps as 2(M) x 2(N); warp tile 64x64 via m16n8k16.
// MODE 1: A loaded fp32 from d, converted in-register, STS to smem (no prep pass).
// MODE 2: A = g_h1s fp16 via cp.async.  B always fp16 cp.async, 4-stage.
#define KTILES 16
#define PITCH  80
#define HALF_STAGE (128 * PITCH)          // 10240 B (A), same for B
#define STAGE_B (2 * HALF_STAGE)          // 20480 B
#define SMEM_B  (4 * STAGE_B)             // 81920 B

template <int MODE>
__global__ __launch_bounds__(128, 2) void gemm_hmma(const float* __restrict__ A32,
                                                    const float* __restrict__ Wc) {
    extern __shared__ char dsmem[];
    __shared__ float red[128][2];
    const int tid = threadIdx.x;
    const int wid = tid >> 5;
    const int lane = tid & 31;
    const int bm = blockIdx.y << 7;
    const int bn = blockIdx.x << 7;
    const int moff = (wid & 1) << 6;      // 0 or 64
    const int noff = (wid >> 1) << 6;     // 0 or 64
    const uint32_t sbase = smem_u32(dsmem);

    const __half* __restrict__ Ah = g_h1s;   // MODE 2 A source
    const __half* __restrict__ B  = (MODE == 1) ? g_b1s : g_b2s;

    uint32_t pa[16];   // MODE 1: prefetched+converted A tile slice (row tid, 32 halves)
    auto loadA32 = [&](int t) {
        const float* p = A32 + (size_t)(bm + tid) * 512 + (t << 5);
#pragma unroll
        for (int c = 0; c < 8; c++) {
            float4 v = *(const float4*)(p + c * 4);
            pa[2*c]   = pack2h(v.x, v.y);
            pa[2*c+1] = pack2h(v.z, v.w);
        }
    };
    auto stsA = [&](int t) {
        const uint32_t dst = sbase + (t & 3) * STAGE_B + (uint32_t)tid * PITCH;
#pragma unroll
        for (int c = 0; c < 8; c++) {
            asm volatile("st.shared.v2.b32 [%0], {%1, %2};"
                :: "r"(dst + c * 8), "r"(pa[2*c]), "r"(pa[2*c+1]) : "memory");
        }
    };
    auto issueB = [&](int t) {
        const int koff = t << 5;
        const uint32_t stB = sbase + (t & 3) * STAGE_B + HALF_STAGE;
#pragma unroll
        for (int i = 0; i < 4; i++) {
            const int id = tid + (i << 7);
            const int row = id >> 2, kc = id & 3;
            CP_ASYNC16(stB + row * PITCH + kc * 16, B + (size_t)(bn + row) * 512 + koff + kc * 8);
        }
        CP_COMMIT();
    };
    auto issueAB = [&](int t) {   // MODE 2: both via cp.async
        const int koff = t << 5;
        const uint32_t stA = sbase + (t & 3) * STAGE_B;
        const uint32_t stB = stA + HALF_STAGE;
#pragma unroll
        for (int i = 0; i < 4; i++) {
            const int id = tid + (i << 7);
            const int row = id >> 2, kc = id & 3;
            CP_ASYNC16(stA + row * PITCH + kc * 16, Ah + (size_t)(bm + row) * 512 + koff + kc * 8);
            CP_ASYNC16(stB + row * PITCH + kc * 16, B + (size_t)(bn + row) * 512 + koff + kc * 8);
        }
        CP_COMMIT();
    };

    float acc[4][8][4];
#pragma unroll
    for (int i = 0; i < 4; i++)
#pragma unroll
        for (int j = 0; j < 8; j++)
#pragma unroll
            for (int r = 0; r < 4; r++) acc[i][j][r] = 0.f;

    if (MODE == 1) {
        loadA32(0);
        issueB(0); issueB(1); issueB(2);
    } else {
        issueAB(0); issueAB(1); issueAB(2);
    }

    // ldmatrix lane addressing
    const int a_row = lane & 15;                 // A: rows m..m+15
    const int a_kb  = ((lane >> 4) & 1) << 4;    // 0 or 16 bytes (k half)
    const int q     = lane >> 3;                 // B quad: 0..3
    const int b_row = ((q >> 1) << 3) + (lane & 7);
    const int b_kb  = (q & 1) << 4;

#pragma unroll 1
    for (int t = 0; t < KTILES; t++) {
        if (MODE == 1) {
            stsA(t);
            if (t + 1 < KTILES) loadA32(t + 1);
        }
        if (t < KTILES - 2)      CP_WAIT(2);
        else if (t == KTILES-2)  CP_WAIT(1);
        else                     CP_WAIT(0);
        __syncthreads();
        if (t + 3 < KTILES) { if (MODE == 1) issueB(t + 3); else issueAB(t + 3); }

        const uint32_t sA = sbase + (t & 3) * STAGE_B;
        const uint32_t sB = sA + HALF_STAGE;
#pragma unroll
        for (int ks = 0; ks < 2; ks++) {
            uint32_t a[4][4];
            uint32_t b[4][4];
#pragma unroll
            for (int mi = 0; mi < 4; mi++) {
                uint32_t addr = sA + (uint32_t)(moff + mi * 16 + a_row) * PITCH + ks * 32 + a_kb;
                LDSM4(a[mi][0], a[mi][1], a[mi][2], a[mi][3], addr);
            }
#pragma unroll
            for (int p = 0; p < 4; p++) {
                uint32_t addr = sB + (uint32_t)(noff + p * 16 + b_row) * PITCH + ks * 32 + b_kb;
                LDSM4(b[p][0], b[p][1], b[p][2], b[p][3], addr);
            }
#pragma unroll
            for (int mi = 0; mi < 4; mi++) {
#pragma unroll
                for (int ni = 0; ni < 8; ni++) {
                    MMA16816(acc[mi][ni], a[mi], b[ni >> 1][(ni & 1) * 2], b[ni >> 1][(ni & 1) * 2 + 1]);
                }
            }
        }
    }

    // ---------------- epilogue ----------------
    const int row0 = moff + (lane >> 2);         // local row base
    const int col0 = noff + ((lane & 3) << 1);   // local col base (even)

    if (MODE == 1) {
#pragma unroll
        for (int mi = 0; mi < 4; mi++) {
#pragma unroll
            for (int h = 0; h < 2; h++) {
                const size_t r = (size_t)bm + row0 + mi * 16 + h * 8;
#pragma unroll
                for (int ni = 0; ni < 8; ni++) {
                    const int col = bn + col0 + ni * 8;
                    float v0 = fmaf(acc[mi][ni][h * 2],     g_sb[col],     g_sb[FDIM + col]);
                    float v1 = fmaf(acc[mi][ni][h * 2 + 1], g_sb[col + 1], g_sb[FDIM + col + 1]);
                    v0 = v0 > 0.f ? v0 : 0.1f * v0;
                    v1 = v1 > 0.f ? v1 : 0.1f * v1;
                    *(uint32_t*)&g_h1s[r * 512 + col] = pack2h(v0, v1);
                }
            }
        }
    } else {
        __syncthreads();
        for (int i = tid; i < 256; i += 128) ((float*)red)[i] = 0.f;
        __syncthreads();
#pragma unroll
        for (int mi = 0; mi < 4; mi++) {
#pragma unroll
            for (int h = 0; h < 2; h++) {
                float p0 = 0.f, p1 = 0.f;
#pragma unroll
                for (int ni = 0; ni < 8; ni++) {
                    const int col = bn + col0 + ni * 8;
                    float v0 = fmaf(acc[mi][ni][h * 2],     g_sb[2*FDIM + col],     g_sb[3*FDIM + col]);
                    float v1 = fmaf(acc[mi][ni][h * 2 + 1], g_sb[2*FDIM + col + 1], g_sb[3*FDIM + col + 1]);
                    v0 = v0 > 0.f ? v0 : 0.1f * v0;
                    v1 = v1 > 0.f ? v1 : 0.1f * v1;
                    p0 = fmaf(v0, Wc[col], p0);        p0 = fmaf(v1, Wc[col + 1], p0);
                    p1 = fmaf(v0, Wc[FDIM + col], p1); p1 = fmaf(v1, Wc[FDIM + col + 1], p1);
                }
                p0 += __shfl_xor_sync(0xFFFFFFFF, p0, 1); p0 += __shfl_xor_sync(0xFFFFFFFF, p0, 2);
                p1 += __shfl_xor_sync(0xFFFFFFFF, p1, 1); p1 += __shfl_xor_sync(0xFFFFFFFF, p1, 2);
                if ((lane & 3) == 0) {
                    const int rl = row0 + mi * 16 + h * 8;
                    atomicAdd(&red[rl][0], p0);
                    atomicAdd(&red[rl][1], p1);
                }
            }
        }
        __syncthreads();
        {
            const int rl = tid;
            g_cpart[blockIdx.x][((size_t)bm + rl) * 2]     = red[rl][0];
            g_cpart[blockIdx.x][((size_t)bm + rl) * 2 + 1] = red[rl][1];
        }
    }
}

// ======================= GCN propagation (4 batches/block, warp-per-row) =======================
// block = (4 b's) x (128 n-rows). Each warp dots w[n] against 8 cs vectors.
__global__ __launch_bounds__(512) void gcn_kernel(const float* __restrict__ w,
                                                  const float* __restrict__ bc,
                                                  float* __restrict__ out) {
    __shared__ float s_cs[8][NADJ];   // [b2*2+k][m]
    const int bg = blockIdx.x >> 2;           // 0..31 (group of 4 b)
    const int nbase = (blockIdx.x & 3) << 7;  // 0,128,256,384
    const int t = threadIdx.x;
    {
        float dm = g_dinv[t];
#pragma unroll
        for (int b2 = 0; b2 < 4; b2++) {
            const int b = bg * 4 + b2;
            size_t base = (size_t)b * (NADJ * 2) + t * 2;
            float v0 = 0.f, v1 = 0.f;
#pragma unroll
            for (int nb = 0; nb < 4; nb++) {
                v0 += g_cpart[nb][base];
                v1 += g_cpart[nb][base + 1];
            }
            s_cs[b2 * 2][t]     = v0 * dm;
            s_cs[b2 * 2 + 1][t] = v1 * dm;
        }
    }
    __syncthreads();
    const int warp = t >> 5, lane = t & 31;
    const float bb0 = bc[0], bb1 = bc[1];
#pragma unroll 1
    for (int j = 0; j < 8; j++) {
        const int n = nbase + warp + j * 16;
        const float4* wr = (const float4*)(w + (size_t)n * NADJ);
        float a[8];
#pragma unroll
        for (int q2 = 0; q2 < 8; q2++) a[q2] = 0.f;
#pragma unroll
        for (int c = 0; c < 4; c++) {
            const int i = lane + c * 32;
            float4 wv = wr[i];
#pragma unroll
            for (int q2 = 0; q2 < 8; q2++) {
                float4 x = ((const float4*)s_cs[q2])[i];
                a[q2] = fmaf(wv.x, x.x, fmaf(wv.y, x.y, fmaf(wv.z, x.z, fmaf(wv.w, x.w, a[q2]))));
            }
        }
#pragma unroll
        for (int o = 16; o > 0; o >>= 1) {
#pragma unroll
            for (int q2 = 0; q2 < 8; q2++) a[q2] += __shfl_xor_sync(0xFFFFFFFF, a[q2], o);
        }
        if (lane == 0) {
            const float dn = g_dinv[n];
#pragma unroll
            for (int b2 = 0; b2 < 4; b2++) {
                size_t oo = ((size_t)(bg * 4 + b2) * NADJ + n) * 2;
                out[oo]     = fmaf(dn, a[b2 * 2]     + s_cs[b2 * 2][n],     bb0);
                out[oo + 1] = fmaf(dn, a[b2 * 2 + 1] + s_cs[b2 * 2 + 1][n], bb1);
            }
        }
    }
}

// ======================= launch =======================
extern "C" void kernel_launch(void* const* d_in, const int* in_sizes, int n_in,
                              void* d_out, int out_size) {
    const float* d   = (const float*)d_in[0];
    const float* w   = (const float*)d_in[1];
    const float* W1  = (const float*)d_in[2];
    const float* b1  = (const float*)d_in[3];
    const float* g1  = (const float*)d_in[4];
    const float* be1 = (const float*)d_in[5];
    const float* m1  = (const float*)d_in[6];
    const float* v1  = (const float*)d_in[7];
    const float* W2  = (const float*)d_in[8];
    const float* b2  = (const float*)d_in[9];
    const float* g2  = (const float*)d_in[10];
    const float* be2 = (const float*)d_in[11];
    const float* m2  = (const float*)d_in[12];
    const float* v2  = (const float*)d_in[13];
    const float* Wc  = (const float*)d_in[14];
    const float* bc  = (const float*)d_in[15];
    float* out = (float*)d_out;

    cudaFuncSetAttribute(gemm_hmma<1>, cudaFuncAttributeMaxDynamicSharedMemorySize, SMEM_B);
    cudaFuncSetAttribute(gemm_hmma<2>, cudaFuncAttributeMaxDynamicSharedMemorySize, SMEM_B);

    prep_mega<<<PREP_BLOCKS, 256>>>(w, W1, W2,
                                    b1, g1, be1, m1, v1, b2, g2, be2, m2, v2);
    gemm_hmma<1><<<dim3(4, MROWS / 128), 128, SMEM_B>>>(d, nullptr);
    gemm_hmma<2><<<dim3(4, MROWS / 128), 128, SMEM_B>>>(nullptr, Wc);
    gcn_kernel<<<128, 512>>>(w, bc, out);
}

// round 13
// speedup vs baseline: 1.2707x; 1.2707x over previous
#include <cuda_runtime.h>
#include <cuda_fp16.h>
#include <stdint.h>
#include <math.h>

#define FDIM 512
#define NADJ 512
#define MROWS 65536

// ======================= helpers =======================
__device__ __forceinline__ uint32_t smem_u32(const void* p) {
    uint32_t a;
    asm("{ .reg .u64 t; cvta.to.shared.u64 t, %1; cvt.u32.u64 %0, t; }" : "=r"(a) : "l"(p));
    return a;
}
#define CP_ASYNC16(sa, ga) asm volatile("cp.async.cg.shared.global [%0], [%1], 16;" :: "r"(sa), "l"(ga) : "memory")
#define CP_COMMIT()        asm volatile("cp.async.commit_group;" ::: "memory")
#define CP_WAIT(n)         asm volatile("cp.async.wait_group %0;" :: "n"(n) : "memory")

#define LDSM4(r0, r1, r2, r3, addr) \
    asm volatile("ldmatrix.sync.aligned.m8n8.x4.shared.b16 {%0,%1,%2,%3}, [%4];" \
        : "=r"(r0), "=r"(r1), "=r"(r2), "=r"(r3) : "r"(addr))

#define MMA16816(d, a, b0, b1) \
    asm volatile("mma.sync.aligned.m16n8k16.row.col.f32.f16.f16.f32 " \
        "{%0,%1,%2,%3}, {%4,%5,%6,%7}, {%8,%9}, {%0,%1,%2,%3};" \
        : "+f"((d)[0]), "+f"((d)[1]), "+f"((d)[2]), "+f"((d)[3]) \
        : "r"((a)[0]), "r"((a)[1]), "r"((a)[2]), "r"((a)[3]), "r"(b0), "r"(b1))

__device__ __forceinline__ uint32_t pack2h(float a, float b) {
    __half2 t = __floats2half2_rn(a, b);
    return *reinterpret_cast<uint32_t*>(&t);
}

// ======================= device scratch =======================
__device__ __half g_a2[(size_t)MROWS * 512];    // d as fp16
__device__ __half g_h1s[(size_t)MROWS * 512];   // h1 as fp16
__device__ __half g_b1s[NADJ * 512];            // W1 fp16
__device__ __half g_b2s[NADJ * 512];            // W2 fp16
__device__ float g_cpart[4][(size_t)MROWS * 2];
__device__ float g_dinv[NADJ];
__device__ float g_sb[4 * FDIM];   // s1, t1, s2, t2

// ======================= fused prep kernel =======================
// blocks [0, 32768)        : convert d fp32 -> fp16
// blocks [32768, 34816)    : convert W1/W2 -> fp16
// block  34816             : fold BN affine scales
// blocks [34817, 35329)    : adjacency row sums -> dinv
#define PREP_BLOCKS (32768 + 2048 + 1 + NADJ)
__global__ void prep_mega(const float4* __restrict__ d, const float* __restrict__ w,
                          const float* __restrict__ W1f, const float* __restrict__ W2f,
                          const float* b1, const float* g1, const float* be1,
                          const float* m1, const float* v1,
                          const float* b2, const float* g2, const float* be2,
                          const float* m2, const float* v2) {
    const int blk = blockIdx.x;
    const int tid = threadIdx.x;
    if (blk < 32768) {
        size_t idx = (size_t)blk * 256 + tid;
        float4 v = d[idx];
        ((uint2*)g_a2)[idx] = make_uint2(pack2h(v.x, v.y), pack2h(v.z, v.w));
    } else if (blk < 34816) {
        int j = blk - 32768;
        int which = j >= 1024;
        int idx = (j & 1023) * 256 + tid;
        const float* W = which ? W2f : W1f;
        __half* out = which ? g_b2s : g_b1s;
        out[idx] = __float2half(W[idx]);
    } else if (blk == 34816) {
        for (int f = tid; f < FDIM; f += 256) {
            float s1 = g1[f] * rsqrtf(v1[f] + 1e-5f);
            g_sb[f]        = s1;
            g_sb[FDIM + f] = (b1[f] - m1[f]) * s1 + be1[f];
            float s2 = g2[f] * rsqrtf(v2[f] + 1e-5f);
            g_sb[2*FDIM + f] = s2;
            g_sb[3*FDIM + f] = (b2[f] - m2[f]) * s2 + be2[f];
        }
    } else {
        __shared__ float red[256];
        int i = blk - 34817;
        float s = w[i * NADJ + tid] + w[i * NADJ + 256 + tid];
        red[tid] = s;
        __syncthreads();
        for (int o = 128; o > 0; o >>= 1) {
            if (tid < o) red[tid] += red[tid + o];
            __syncthreads();
        }
        if (tid == 0) {
            float di = rsqrtf(red[0] + 1.0f);
            if (isinf(di)) di = 0.f;
            g_dinv[i] = di;
        }
    }
}

// ======================= HMMA GEMM (pure fp16, round-8/11 config) =======================
// C[128 x 128] per block. K = 512 in 16 k-tiles of 32.
// 128 threads = 4 warps as 2(M) x 2(N); warp tile 64x64 via m16n8k16.
// 4-stage cp.async pipeline. smem pitch 80 B (conflict-free ldmatrix phases).
#define KTILES 16
#define PITCH  80
#define HALF_STAGE (128 * PITCH)          // 10240 B (A), same for B
#define STAGE_B (2 * HALF_STAGE)          // 20480 B
#define SMEM_B  (4 * STAGE_B)             // 81920 B

template <int MODE>
__global__ __launch_bounds__(128, 2) void gemm_hmma(const float* __restrict__ Wc) {
    extern __shared__ char dsmem[];
    __shared__ float red[128][2];
    const int tid = threadIdx.x;
    const int wid = tid >> 5;
    const int lane = tid & 31;
    const int bm = blockIdx.y << 7;
    const int bn = blockIdx.x << 7;
    const int moff = (wid & 1) << 6;      // 0 or 64
    const int noff = (wid >> 1) << 6;     // 0 or 64
    const uint32_t sbase = smem_u32(dsmem);

    const __half* __restrict__ A = (MODE == 1) ? g_a2 : g_h1s;
    const __half* __restrict__ B = (MODE == 1) ? g_b1s : g_b2s;

    auto issue = [&](int t) {
        const int s = t & 3;
        const int koff = t << 5;
        const uint32_t stA = sbase + s * STAGE_B;
        const uint32_t stB = stA + HALF_STAGE;
#pragma unroll
        for (int i = 0; i < 4; i++) {
            const int id = tid + (i << 7);       // 0..511
            const int row = id >> 2, kc = id & 3;
            CP_ASYNC16(stA + row * PITCH + kc * 16, A + (size_t)(bm + row) * 512 + koff + kc * 8);
            CP_ASYNC16(stB + row * PITCH + kc * 16, B + (size_t)(bn + row) * 512 + koff + kc * 8);
        }
        CP_COMMIT();
    };

    float acc[4][8][4];
#pragma unroll
    for (int i = 0; i < 4; i++)
#pragma unroll
        for (int j = 0; j < 8; j++)
#pragma unroll
            for (int r = 0; r < 4; r++) acc[i][j][r] = 0.f;

    issue(0); issue(1); issue(2);

    // ldmatrix lane addressing
    const int a_row = lane & 15;                 // A: rows m..m+15
    const int a_kb  = ((lane >> 4) & 1) << 4;    // 0 or 16 bytes (k half)
    const int q     = lane >> 3;                 // B quad: 0..3
    const int b_row = ((q >> 1) << 3) + (lane & 7);
    const int b_kb  = (q & 1) << 4;

#pragma unroll 1
    for (int t = 0; t < KTILES; t++) {
        if (t < KTILES - 2)      CP_WAIT(2);
        else if (t == KTILES-2)  CP_WAIT(1);
        else                     CP_WAIT(0);
        __syncthreads();
        if (t + 3 < KTILES) issue(t + 3);

        const uint32_t sA = sbase + (t & 3) * STAGE_B;
        const uint32_t sB = sA + HALF_STAGE;
#pragma unroll
        for (int ks = 0; ks < 2; ks++) {
            uint32_t a[4][4];
            uint32_t b[4][4];
#pragma unroll
            for (int mi = 0; mi < 4; mi++) {
                uint32_t addr = sA + (uint32_t)(moff + mi * 16 + a_row) * PITCH + ks * 32 + a_kb;
                LDSM4(a[mi][0], a[mi][1], a[mi][2], a[mi][3], addr);
            }
#pragma unroll
            for (int p = 0; p < 4; p++) {
                uint32_t addr = sB + (uint32_t)(noff + p * 16 + b_row) * PITCH + ks * 32 + b_kb;
                LDSM4(b[p][0], b[p][1], b[p][2], b[p][3], addr);
            }
#pragma unroll
            for (int mi = 0; mi < 4; mi++) {
#pragma unroll
                for (int ni = 0; ni < 8; ni++) {
                    MMA16816(acc[mi][ni], a[mi], b[ni >> 1][(ni & 1) * 2], b[ni >> 1][(ni & 1) * 2 + 1]);
                }
            }
        }
    }

    // ---------------- epilogue ----------------
    const int row0 = moff + (lane >> 2);         // local row base
    const int col0 = noff + ((lane & 3) << 1);   // local col base (even)

    if (MODE == 1) {
#pragma unroll
        for (int mi = 0; mi < 4; mi++) {
#pragma unroll
            for (int h = 0; h < 2; h++) {
                const size_t r = (size_t)bm + row0 + mi * 16 + h * 8;
#pragma unroll
                for (int ni = 0; ni < 8; ni++) {
                    const int col = bn + col0 + ni * 8;
                    float v0 = fmaf(acc[mi][ni][h * 2],     g_sb[col],     g_sb[FDIM + col]);
                    float v1 = fmaf(acc[mi][ni][h * 2 + 1], g_sb[col + 1], g_sb[FDIM + col + 1]);
                    v0 = v0 > 0.f ? v0 : 0.1f * v0;
                    v1 = v1 > 0.f ? v1 : 0.1f * v1;
                    *(uint32_t*)&g_h1s[r * 512 + col] = pack2h(v0, v1);
                }
            }
        }
    } else {
        __syncthreads();
        for (int i = tid; i < 256; i += 128) ((float*)red)[i] = 0.f;
        __syncthreads();
#pragma unroll
        for (int mi = 0; mi < 4; mi++) {
#pragma unroll
            for (int h = 0; h < 2; h++) {
                float p0 = 0.f, p1 = 0.f;
#pragma unroll
                for (int ni = 0; ni < 8; ni++) {
                    const int col = bn + col0 + ni * 8;
                    float v0 = fmaf(acc[mi][ni][h * 2],     g_sb[2*FDIM + col],     g_sb[3*FDIM + col]);
                    float v1 = fmaf(acc[mi][ni][h * 2 + 1], g_sb[2*FDIM + col + 1], g_sb[3*FDIM + col + 1]);
                    v0 = v0 > 0.f ? v0 : 0.1f * v0;
                    v1 = v1 > 0.f ? v1 : 0.1f * v1;
                    p0 = fmaf(v0, Wc[col], p0);        p0 = fmaf(v1, Wc[col + 1], p0);
                    p1 = fmaf(v0, Wc[FDIM + col], p1); p1 = fmaf(v1, Wc[FDIM + col + 1], p1);
                }
                p0 += __shfl_xor_sync(0xFFFFFFFF, p0, 1); p0 += __shfl_xor_sync(0xFFFFFFFF, p0, 2);
                p1 += __shfl_xor_sync(0xFFFFFFFF, p1, 1); p1 += __shfl_xor_sync(0xFFFFFFFF, p1, 2);
                if ((lane & 3) == 0) {
                    const int rl = row0 + mi * 16 + h * 8;
                    atomicAdd(&red[rl][0], p0);
                    atomicAdd(&red[rl][1], p1);
                }
            }
        }
        __syncthreads();
        {
            const int rl = tid;
            g_cpart[blockIdx.x][((size_t)bm + rl) * 2]     = red[rl][0];
            g_cpart[blockIdx.x][((size_t)bm + rl) * 2 + 1] = red[rl][1];
        }
    }
}

// ======================= GCN propagation (4 batches/block, warp-per-row) =======================
// block = (4 b's) x (128 n-rows). Each warp dots w[n] against 8 cs vectors.
__global__ __launch_bounds__(512) void gcn_kernel(const float* __restrict__ w,
                                                  const float* __restrict__ bc,
                                                  float* __restrict__ out) {
    __shared__ float s_cs[8][NADJ];   // [b2*2+k][m]
    const int bg = blockIdx.x >> 2;           // 0..31 (group of 4 b)
    const int nbase = (blockIdx.x & 3) << 7;  // 0,128,256,384
    const int t = threadIdx.x;
    {
        float dm = g_dinv[t];
#pragma unroll
        for (int b2 = 0; b2 < 4; b2++) {
            const int b = bg * 4 + b2;
            size_t base = (size_t)b * (NADJ * 2) + t * 2;
            float v0 = 0.f, v1 = 0.f;
#pragma unroll
            for (int nb = 0; nb < 4; nb++) {
                v0 += g_cpart[nb][base];
                v1 += g_cpart[nb][base + 1];
            }
            s_cs[b2 * 2][t]     = v0 * dm;
            s_cs[b2 * 2 + 1][t] = v1 * dm;
        }
    }
    __syncthreads();
    const int warp = t >> 5, lane = t & 31;
    const float bb0 = bc[0], bb1 = bc[1];
#pragma unroll 1
    for (int j = 0; j < 8; j++) {
        const int n = nbase + warp + j * 16;
        const float4* wr = (const float4*)(w + (size_t)n * NADJ);
        float a[8];
#pragma unroll
        for (int q2 = 0; q2 < 8; q2++) a[q2] = 0.f;
#pragma unroll
        for (int c = 0; c < 4; c++) {
            const int i = lane + c * 32;
            float4 wv = wr[i];
#pragma unroll
            for (int q2 = 0; q2 < 8; q2++) {
                float4 x = ((const float4*)s_cs[q2])[i];
                a[q2] = fmaf(wv.x, x.x, fmaf(wv.y, x.y, fmaf(wv.z, x.z, fmaf(wv.w, x.w, a[q2]))));
            }
        }
#pragma unroll
        for (int o = 16; o > 0; o >>= 1) {
#pragma unroll
            for (int q2 = 0; q2 < 8; q2++) a[q2] += __shfl_xor_sync(0xFFFFFFFF, a[q2], o);
        }
        if (lane == 0) {
            const float dn = g_dinv[n];
#pragma unroll
            for (int b2 = 0; b2 < 4; b2++) {
                size_t oo = ((size_t)(bg * 4 + b2) * NADJ + n) * 2;
                out[oo]     = fmaf(dn, a[b2 * 2]     + s_cs[b2 * 2][n],     bb0);
                out[oo + 1] = fmaf(dn, a[b2 * 2 + 1] + s_cs[b2 * 2 + 1][n], bb1);
            }
        }
    }
}

// ======================= launch =======================
extern "C" void kernel_launch(void* const* d_in, const int* in_sizes, int n_in,
                              void* d_out, int out_size) {
    const float* d   = (const float*)d_in[0];
    const float* w   = (const float*)d_in[1];
    const float* W1  = (const float*)d_in[2];
    const float* b1  = (const float*)d_in[3];
    const float* g1  = (const float*)d_in[4];
    const float* be1 = (const float*)d_in[5];
    const float* m1  = (const float*)d_in[6];
    const float* v1  = (const float*)d_in[7];
    const float* W2  = (const float*)d_in[8];
    const float* b2  = (const float*)d_in[9];
    const float* g2  = (const float*)d_in[10];
    const float* be2 = (const float*)d_in[11];
    const float* m2  = (const float*)d_in[12];
    const float* v2  = (const float*)d_in[13];
    const float* Wc  = (const float*)d_in[14];
    const float* bc  = (const float*)d_in[15];
    float* out = (float*)d_out;

    cudaFuncSetAttribute(gemm_hmma<1>, cudaFuncAttributeMaxDynamicSharedMemorySize, SMEM_B);
    cudaFuncSetAttribute(gemm_hmma<2>, cudaFuncAttributeMaxDynamicSharedMemorySize, SMEM_B);

    prep_mega<<<PREP_BLOCKS, 256>>>((const float4*)d, w, W1, W2,
                                    b1, g1, be1, m1, v1, b2, g2, be2, m2, v2);
    gemm_hmma<1><<<dim3(4, MROWS / 128), 128, SMEM_B>>>(nullptr);
    gemm_hmma<2><<<dim3(4, MROWS / 128), 128, SMEM_B>>>(Wc);
    gcn_kernel<<<128, 512>>>(w, bc, out);
}